// round 6
// baseline (speedup 1.0000x reference)
#include <cuda_runtime.h>
#include <math.h>
#include <stdint.h>

#define MAX_E 3200000
#define MAX_N 100000
#define FIN 128
#define H1D 64
#define H2D 32
#define NCLS 10
#define SCAN_B 512
#define MAX_BLKS ((MAX_N + SCAN_B) / SCAN_B + 2)

// ---------------- scratch (device globals; referenced directly) --------------
__device__ __align__(16) int   g_indeg[MAX_N];
__device__ __align__(16) int   g_off[MAX_N + 1];
__device__ __align__(16) int   g_pos[MAX_N];
__device__ __align__(16) int   g_part[MAX_N];
__device__ __align__(16) int   g_bsum[MAX_BLKS];
__device__ __align__(16) float g_dinv[MAX_N];
__device__ __align__(16) int2  g_edge[MAX_E];      // (src, norm bits) packed
__device__ __align__(16) float g_h1[MAX_N * H1D];
__device__ __align__(16) float g_a1[MAX_N * H1D];
__device__ __align__(16) float g_h2[MAX_N * H2D];

// ---------------- f32x2 helpers (sm_103a packed dual-FMA) --------------------
__device__ __forceinline__ uint64_t pk2(float lo, float hi) {
    uint64_t r; asm("mov.b64 %0, {%1,%2};" : "=l"(r) : "f"(lo), "f"(hi)); return r;
}
__device__ __forceinline__ void upk2(uint64_t v, float& lo, float& hi) {
    asm("mov.b64 {%0,%1}, %2;" : "=f"(lo), "=f"(hi) : "l"(v));
}
__device__ __forceinline__ void fma2(uint64_t& d, uint64_t a, uint64_t b) {
    asm("fma.rn.f32x2 %0, %1, %2, %0;" : "+l"(d) : "l"(a), "l"(b));
}

// ---------------- CSR build ---------------------------------------------------
__global__ void k_zero(int N) {
    int i = blockIdx.x * blockDim.x + threadIdx.x;
    if (i < N) g_indeg[i] = 0;
}

__global__ void k_count(const int* __restrict__ ei, int E) {
    int e2 = (blockIdx.x * blockDim.x + threadIdx.x) * 2;
    if (e2 + 1 < E) {
        int2 dd = *(const int2*)&ei[E + e2];
        atomicAdd(&g_indeg[dd.x], 1);
        atomicAdd(&g_indeg[dd.y], 1);
    } else if (e2 < E) {
        atomicAdd(&g_indeg[ei[E + e2]], 1);
    }
}

__global__ void k_scan1(int N) {
    __shared__ int sm[SCAN_B];
    int gid = blockIdx.x * SCAN_B + threadIdx.x;
    int v = (gid < N) ? g_indeg[gid] : 0;
    sm[threadIdx.x] = v;
    __syncthreads();
#pragma unroll
    for (int s = 1; s < SCAN_B; s <<= 1) {
        int t = (threadIdx.x >= (unsigned)s) ? sm[threadIdx.x - s] : 0;
        __syncthreads();
        sm[threadIdx.x] += t;
        __syncthreads();
    }
    if (gid < N) g_part[gid] = sm[threadIdx.x] - v;  // exclusive within block
    if (threadIdx.x == SCAN_B - 1) g_bsum[blockIdx.x] = sm[threadIdx.x];
}

// parallel exclusive scan of block sums (nb <= 256)
__global__ void k_scan2(int nb) {
    __shared__ int sm[256];
    int t = threadIdx.x;
    int v = (t < nb) ? g_bsum[t] : 0;
    sm[t] = v;
    __syncthreads();
#pragma unroll
    for (int s = 1; s < 256; s <<= 1) {
        int u = (t >= (unsigned)s) ? sm[t - s] : 0;
        __syncthreads();
        sm[t] += u;
        __syncthreads();
    }
    if (t < nb) g_bsum[t] = sm[t] - v;  // exclusive
}

// offsets + pos + dinv in one pass
__global__ void k_scan3(int N, int E) {
    int gid = blockIdx.x * blockDim.x + threadIdx.x;
    if (gid < N) {
        int o = g_part[gid] + g_bsum[gid / SCAN_B];
        g_off[gid] = o;
        g_pos[gid] = o;
        g_dinv[gid] = rsqrtf((float)g_indeg[gid] + 1.0f);
    }
    if (gid == 0) g_off[N] = E;
}

__global__ void k_fill(const int* __restrict__ ei, int E) {
    int e2 = (blockIdx.x * blockDim.x + threadIdx.x) * 2;
    if (e2 + 1 < E) {
        int2 ss = *(const int2*)&ei[e2];
        int2 dd = *(const int2*)&ei[E + e2];
        int p0 = atomicAdd(&g_pos[dd.x], 1);
        int p1 = atomicAdd(&g_pos[dd.y], 1);
        g_edge[p0] = make_int2(ss.x, __float_as_int(g_dinv[ss.x] * g_dinv[dd.x]));
        g_edge[p1] = make_int2(ss.y, __float_as_int(g_dinv[ss.y] * g_dinv[dd.y]));
    } else if (e2 < E) {
        int s = ei[e2], d = ei[E + e2];
        int p = atomicAdd(&g_pos[d], 1);
        g_edge[p] = make_int2(s, __float_as_int(g_dinv[s] * g_dinv[d]));
    }
}

// ---------------- f32x2 register-tiled GEMM ----------------------------------
// out[N,ODIM] = (relu?)X[N,KDIM] @ W[KDIM,ODIM].  128 threads/block.
// thread tile: 4 rows x 8 cols (4 f32x2 pairs).
template <int KDIM, int ODIM, bool RELU_IN, int LAYER>
__global__ void k_gemm(const float* __restrict__ Xparam, const float* __restrict__ Wg,
                       int N) {
    const float* X  = (LAYER == 1) ? Xparam : g_a1;
    float*      out = (LAYER == 1) ? g_h1   : g_h2;

    constexpr int COLG = ODIM / 8;        // col groups (8 cols each)
    constexpr int ROWG = 128 / COLG;      // row groups (4 rows each)
    constexpr int RM   = ROWG * 4;        // rows per block
    __shared__ float Wsm[KDIM * ODIM];
    __shared__ float Xsm[RM * KDIM];

    int tid = threadIdx.x;
    for (int i = tid; i < KDIM * ODIM; i += 128) Wsm[i] = Wg[i];

    int row0 = blockIdx.x * RM;
    {
        float4* X4sm = (float4*)Xsm;
        const float4* X4 = (const float4*)X;
        for (int i4 = tid; i4 < RM * (KDIM / 4); i4 += 128) {
            int r  = i4 / (KDIM / 4);
            int kk = i4 - r * (KDIM / 4);
            int gr = row0 + r;
            float4 v = make_float4(0.f, 0.f, 0.f, 0.f);
            if (gr < N) v = X4[(size_t)gr * (KDIM / 4) + kk];
            if (RELU_IN) {
                v.x = fmaxf(v.x, 0.f); v.y = fmaxf(v.y, 0.f);
                v.z = fmaxf(v.z, 0.f); v.w = fmaxf(v.w, 0.f);
            }
            X4sm[i4] = v;
        }
    }
    __syncthreads();

    int tx = tid % COLG;          // col group
    int ty = tid / COLG;          // row group
    int c0 = tx * 8;
    int r0 = ty * 4;

    uint64_t acc[4][4];
#pragma unroll
    for (int r = 0; r < 4; r++)
#pragma unroll
        for (int p = 0; p < 4; p++) acc[r][p] = 0ULL;  // (0.0f, 0.0f)

    for (int k = 0; k < KDIM; k += 4) {
        uint64_t wp[4][4];
#pragma unroll
        for (int kk = 0; kk < 4; kk++) {
            const float4* wrow = (const float4*)&Wsm[(k + kk) * ODIM + c0];
            float4 a = wrow[0], b = wrow[1];
            wp[kk][0] = pk2(a.x, a.y); wp[kk][1] = pk2(a.z, a.w);
            wp[kk][2] = pk2(b.x, b.y); wp[kk][3] = pk2(b.z, b.w);
        }
#pragma unroll
        for (int r = 0; r < 4; r++) {
            float4 xv = *(const float4*)&Xsm[(r0 + r) * KDIM + k];
            uint64_t x0 = pk2(xv.x, xv.x), x1 = pk2(xv.y, xv.y);
            uint64_t x2 = pk2(xv.z, xv.z), x3 = pk2(xv.w, xv.w);
#pragma unroll
            for (int p = 0; p < 4; p++) {
                fma2(acc[r][p], x0, wp[0][p]);
                fma2(acc[r][p], x1, wp[1][p]);
                fma2(acc[r][p], x2, wp[2][p]);
                fma2(acc[r][p], x3, wp[3][p]);
            }
        }
    }

#pragma unroll
    for (int r = 0; r < 4; r++) {
        int gr = row0 + r0 + r;
        if (gr >= N) continue;
        float4 o0, o1;
        upk2(acc[r][0], o0.x, o0.y); upk2(acc[r][1], o0.z, o0.w);
        upk2(acc[r][2], o1.x, o1.y); upk2(acc[r][3], o1.z, o1.w);
        float4* dst = (float4*)&out[(size_t)gr * ODIM + c0];
        dst[0] = o0;
        dst[1] = o1;
    }
}

// -------- CSR gather layer 1: a1[i] = sum_j h1[s_j]*n_j + h1[i]*dinv^2 + b ---
__global__ void k_gather64(const float* __restrict__ b, int N) {
    const float* h  = g_h1;
    float*      out = g_a1;
    constexpr int F = H1D, C = F / 32;

    int node = blockIdx.x * (blockDim.x >> 5) + (threadIdx.x >> 5);
    int lane = threadIdx.x & 31;
    if (node >= N) return;

    int beg = g_off[node];
    int end = g_off[node + 1];

    float acc[C];
#pragma unroll
    for (int c = 0; c < C; c++) acc[c] = 0.0f;

    int j = beg;
    for (; j + 3 < end; j += 4) {
        int2 m0 = __ldg(&g_edge[j + 0]);
        int2 m1 = __ldg(&g_edge[j + 1]);
        int2 m2 = __ldg(&g_edge[j + 2]);
        int2 m3 = __ldg(&g_edge[j + 3]);
        const float* r0 = h + (size_t)m0.x * F;
        const float* r1 = h + (size_t)m1.x * F;
        const float* r2 = h + (size_t)m2.x * F;
        const float* r3 = h + (size_t)m3.x * F;
        float n0 = __int_as_float(m0.y), n1 = __int_as_float(m1.y);
        float n2 = __int_as_float(m2.y), n3 = __int_as_float(m3.y);
#pragma unroll
        for (int c = 0; c < C; c++) {
            acc[c] += __ldg(&r0[lane + 32 * c]) * n0;
            acc[c] += __ldg(&r1[lane + 32 * c]) * n1;
            acc[c] += __ldg(&r2[lane + 32 * c]) * n2;
            acc[c] += __ldg(&r3[lane + 32 * c]) * n3;
        }
    }
    for (; j < end; j++) {
        int2 m = __ldg(&g_edge[j]);
        const float* r = h + (size_t)m.x * F;
        float nm = __int_as_float(m.y);
#pragma unroll
        for (int c = 0; c < C; c++) acc[c] += __ldg(&r[lane + 32 * c]) * nm;
    }

    float di = g_dinv[node];
    float d2 = di * di;
    const float* hr = h + (size_t)node * F;
#pragma unroll
    for (int c = 0; c < C; c++) {
        int col = lane + 32 * c;
        out[(size_t)node * F + col] = acc[c] + hr[col] * d2 + b[col];
    }
}

// -------- CSR gather layer 2 + relu + classifier + log_softmax ---------------
// F=32: one warp per node, lane = feature column. Fully fused epilogue.
__global__ void k_gather32f(const float* __restrict__ b, const float* __restrict__ Wc,
                            const float* __restrict__ bc, float* __restrict__ outp,
                            int N) {
    constexpr int F = H2D;
    __shared__ float WcSm[H2D * NCLS];
    __shared__ float bcSm[NCLS];
    int tid = threadIdx.x;
    for (int i = tid; i < H2D * NCLS; i += blockDim.x) WcSm[i] = Wc[i];
    if (tid < NCLS) bcSm[tid] = bc[tid];
    __syncthreads();

    int node = blockIdx.x * (blockDim.x >> 5) + (tid >> 5);
    int lane = tid & 31;
    if (node >= N) return;  // warp-uniform

    const float* h = g_h2;
    int beg = g_off[node];
    int end = g_off[node + 1];

    float acc = 0.0f;
    int j = beg;
    for (; j + 3 < end; j += 4) {
        int2 m0 = __ldg(&g_edge[j + 0]);
        int2 m1 = __ldg(&g_edge[j + 1]);
        int2 m2 = __ldg(&g_edge[j + 2]);
        int2 m3 = __ldg(&g_edge[j + 3]);
        acc += __ldg(&h[(size_t)m0.x * F + lane]) * __int_as_float(m0.y);
        acc += __ldg(&h[(size_t)m1.x * F + lane]) * __int_as_float(m1.y);
        acc += __ldg(&h[(size_t)m2.x * F + lane]) * __int_as_float(m2.y);
        acc += __ldg(&h[(size_t)m3.x * F + lane]) * __int_as_float(m3.y);
    }
    for (; j < end; j++) {
        int2 m = __ldg(&g_edge[j]);
        acc += __ldg(&h[(size_t)m.x * F + lane]) * __int_as_float(m.y);
    }

    float di = g_dinv[node];
    float x = acc + h[(size_t)node * F + lane] * di * di + b[lane];
    x = fmaxf(x, 0.0f);  // relu before classifier

    // logits: lg[c] = sum_lane x * Wc[lane][c]  (warp butterfly on 10-vector)
    float p[NCLS];
#pragma unroll
    for (int c = 0; c < NCLS; c++) p[c] = x * WcSm[lane * NCLS + c];
#pragma unroll
    for (int s = 16; s > 0; s >>= 1)
#pragma unroll
        for (int c = 0; c < NCLS; c++)
            p[c] += __shfl_xor_sync(0xffffffffu, p[c], s);

    float lg[NCLS];
#pragma unroll
    for (int c = 0; c < NCLS; c++) lg[c] = p[c] + bcSm[c];
    float mx = lg[0];
#pragma unroll
    for (int c = 1; c < NCLS; c++) mx = fmaxf(mx, lg[c]);
    float sum = 0.0f;
#pragma unroll
    for (int c = 0; c < NCLS; c++) sum += __expf(lg[c] - mx);
    float lse = mx + logf(sum);

    if (lane < NCLS) outp[(size_t)node * NCLS + lane] = lg[lane] - lse;
}

// ---------------- launch (kernel launches ONLY) ------------------------------
extern "C" void kernel_launch(void* const* d_in, const int* in_sizes, int n_in,
                              void* d_out, int out_size) {
    const float* feat = (const float*)d_in[0];
    const int*   ei   = (const int*)d_in[1];    // int32 (JAX x64 disabled)
    const float* W1   = (const float*)d_in[2];
    const float* b1   = (const float*)d_in[3];
    const float* W2   = (const float*)d_in[4];
    const float* b2   = (const float*)d_in[5];
    const float* Wc   = (const float*)d_in[6];
    const float* bc   = (const float*)d_in[7];

    int N = in_sizes[0] / FIN;
    int E = in_sizes[1] / 2;

    const int T = 256;
    int nb = (N + SCAN_B - 1) / SCAN_B;
    int Eh = (E + 1) / 2;

    // CSR build
    k_zero<<<(N + T - 1) / T, T>>>(N);
    k_count<<<(Eh + T - 1) / T, T>>>(ei, E);
    k_scan1<<<nb, SCAN_B>>>(N);
    k_scan2<<<1, 256>>>(nb);
    k_scan3<<<(N + T - 1) / T, T>>>(N, E);
    k_fill<<<(Eh + T - 1) / T, T>>>(ei, E);

    // layer 1
    k_gemm<FIN, H1D, false, 1><<<(N + 63) / 64, 128>>>(feat, W1, N);
    k_gather64<<<(N + 7) / 8, 256>>>(b1, N);

    // layer 2 + fused classifier/log_softmax
    k_gemm<H1D, H2D, true, 2><<<(N + 127) / 128, 128>>>(nullptr, W2, N);
    k_gather32f<<<(N + 7) / 8, 256>>>(b2, Wc, bc, (float*)d_out, N);
}

// round 7
// speedup vs baseline: 1.0017x; 1.0017x over previous
#include <cuda_runtime.h>
#include <math.h>
#include <stdint.h>

#define MAX_E 3200000
#define MAX_N 100000
#define FIN 128
#define H1D 64
#define H2D 32
#define NCLS 10
#define SCAN_B 512
#define MAX_BLKS ((MAX_N + SCAN_B) / SCAN_B + 2)

// ---------------- scratch (device globals; referenced directly) --------------
__device__ __align__(16) int   g_indeg[MAX_N];
__device__ __align__(16) int   g_off[MAX_N + 1];
__device__ __align__(16) int   g_pos[MAX_N];
__device__ __align__(16) int   g_part[MAX_N];
__device__ __align__(16) int   g_bsum[MAX_BLKS];
__device__ __align__(16) float g_dinv[MAX_N];
__device__ __align__(16) int2  g_edge[MAX_E];      // (src, norm bits) packed
__device__ __align__(16) float g_h1[MAX_N * H1D];
__device__ __align__(16) float g_a1[MAX_N * H1D];
__device__ __align__(16) float g_h2[MAX_N * H2D];

// ---------------- CSR build ---------------------------------------------------
__global__ void k_zero(int N) {
    int i = blockIdx.x * blockDim.x + threadIdx.x;
    if (i < N) g_indeg[i] = 0;
}

__global__ void k_count(const int* __restrict__ ei, int E) {
    int e2 = (blockIdx.x * blockDim.x + threadIdx.x) * 2;
    if (e2 + 1 < E) {
        int2 dd = *(const int2*)&ei[E + e2];
        atomicAdd(&g_indeg[dd.x], 1);
        atomicAdd(&g_indeg[dd.y], 1);
    } else if (e2 < E) {
        atomicAdd(&g_indeg[ei[E + e2]], 1);
    }
}

__global__ void k_scan1(int N) {
    __shared__ int sm[SCAN_B];
    int gid = blockIdx.x * SCAN_B + threadIdx.x;
    int v = (gid < N) ? g_indeg[gid] : 0;
    sm[threadIdx.x] = v;
    __syncthreads();
#pragma unroll
    for (int s = 1; s < SCAN_B; s <<= 1) {
        int t = (threadIdx.x >= (unsigned)s) ? sm[threadIdx.x - s] : 0;
        __syncthreads();
        sm[threadIdx.x] += t;
        __syncthreads();
    }
    if (gid < N) g_part[gid] = sm[threadIdx.x] - v;  // exclusive within block
    if (threadIdx.x == SCAN_B - 1) g_bsum[blockIdx.x] = sm[threadIdx.x];
}

// parallel exclusive scan of block sums (nb <= 256)
__global__ void k_scan2(int nb) {
    __shared__ int sm[256];
    int t = threadIdx.x;
    int v = (t < nb) ? g_bsum[t] : 0;
    sm[t] = v;
    __syncthreads();
#pragma unroll
    for (int s = 1; s < 256; s <<= 1) {
        int u = (t >= (unsigned)s) ? sm[t - s] : 0;
        __syncthreads();
        sm[t] += u;
        __syncthreads();
    }
    if (t < nb) g_bsum[t] = sm[t] - v;  // exclusive
}

// offsets + pos + dinv in one pass
__global__ void k_scan3(int N, int E) {
    int gid = blockIdx.x * blockDim.x + threadIdx.x;
    if (gid < N) {
        int o = g_part[gid] + g_bsum[gid / SCAN_B];
        g_off[gid] = o;
        g_pos[gid] = o;
        g_dinv[gid] = rsqrtf((float)g_indeg[gid] + 1.0f);
    }
    if (gid == 0) g_off[N] = E;
}

__global__ void k_fill(const int* __restrict__ ei, int E) {
    int e2 = (blockIdx.x * blockDim.x + threadIdx.x) * 2;
    if (e2 + 1 < E) {
        int2 ss = *(const int2*)&ei[e2];
        int2 dd = *(const int2*)&ei[E + e2];
        int p0 = atomicAdd(&g_pos[dd.x], 1);
        int p1 = atomicAdd(&g_pos[dd.y], 1);
        g_edge[p0] = make_int2(ss.x, __float_as_int(g_dinv[ss.x] * g_dinv[dd.x]));
        g_edge[p1] = make_int2(ss.y, __float_as_int(g_dinv[ss.y] * g_dinv[dd.y]));
    } else if (e2 < E) {
        int s = ei[e2], d = ei[E + e2];
        int p = atomicAdd(&g_pos[d], 1);
        g_edge[p] = make_int2(s, __float_as_int(g_dinv[s] * g_dinv[d]));
    }
}

// ---------------- dense GEMM (R5-proven): out = (relu?)X @ W -----------------
// LAYER 1: X = feat param, out = g_h1. LAYER 2: X = g_a1, out = g_h2.
template <int KDIM, int ODIM, bool RELU_IN, int LAYER>
__global__ void k_gemm(const float* __restrict__ Xparam, const float* __restrict__ Wg,
                       int N) {
    const float* X  = (LAYER == 1) ? Xparam : g_a1;
    float*      out = (LAYER == 1) ? g_h1   : g_h2;

    constexpr int NL  = 256 / ODIM;   // row-lanes
    constexpr int RPT = 4;            // rows per thread
    constexpr int RPB = NL * RPT;     // rows per block
    __shared__ float Wsm[KDIM * ODIM];
    __shared__ float Xsm[RPB * KDIM];

    int tid = threadIdx.x;
    for (int i = tid; i < KDIM * ODIM; i += 256) Wsm[i] = Wg[i];

    int row0 = blockIdx.x * RPB;
    for (int i = tid; i < RPB * KDIM; i += 256) {
        int r = i / KDIM, k = i - r * KDIM;
        int gr = row0 + r;
        float v = (gr < N) ? X[(size_t)gr * KDIM + k] : 0.0f;
        if (RELU_IN) v = fmaxf(v, 0.0f);
        Xsm[i] = v;
    }
    __syncthreads();

    int col = tid % ODIM;
    int rl  = tid / ODIM;
    float acc[RPT];
#pragma unroll
    for (int j = 0; j < RPT; j++) acc[j] = 0.0f;

#pragma unroll 4
    for (int k = 0; k < KDIM; k++) {
        float w = Wsm[k * ODIM + col];
#pragma unroll
        for (int j = 0; j < RPT; j++)
            acc[j] += Xsm[(rl * RPT + j) * KDIM + k] * w;
    }
#pragma unroll
    for (int j = 0; j < RPT; j++) {
        int gr = row0 + rl * RPT + j;
        if (gr < N) out[(size_t)gr * ODIM + col] = acc[j];
    }
}

// -------- CSR gather layer 1: a1[i] = sum_j h1[s_j]*n_j + h1[i]*dinv^2 + b ---
// lane reads float2 at column lane*2 -> one 8B load per edge per lane
__global__ void k_gather64(const float* __restrict__ b, int N) {
    const float2* h = (const float2*)g_h1;
    float2*     out = (float2*)g_a1;
    constexpr int C2 = H1D / 2;   // 32 float2 per row: one per lane

    int node = blockIdx.x * (blockDim.x >> 5) + (threadIdx.x >> 5);
    int lane = threadIdx.x & 31;
    if (node >= N) return;

    int beg = g_off[node];
    int end = g_off[node + 1];

    float ax = 0.0f, ay = 0.0f;
    int j = beg;
    for (; j + 3 < end; j += 4) {
        int2 m0 = __ldg(&g_edge[j + 0]);
        int2 m1 = __ldg(&g_edge[j + 1]);
        int2 m2 = __ldg(&g_edge[j + 2]);
        int2 m3 = __ldg(&g_edge[j + 3]);
        float2 v0 = __ldg(&h[(size_t)m0.x * C2 + lane]);
        float2 v1 = __ldg(&h[(size_t)m1.x * C2 + lane]);
        float2 v2 = __ldg(&h[(size_t)m2.x * C2 + lane]);
        float2 v3 = __ldg(&h[(size_t)m3.x * C2 + lane]);
        float n0 = __int_as_float(m0.y), n1 = __int_as_float(m1.y);
        float n2 = __int_as_float(m2.y), n3 = __int_as_float(m3.y);
        ax += v0.x * n0 + v1.x * n1 + v2.x * n2 + v3.x * n3;
        ay += v0.y * n0 + v1.y * n1 + v2.y * n2 + v3.y * n3;
    }
    for (; j < end; j++) {
        int2 m = __ldg(&g_edge[j]);
        float2 v = __ldg(&h[(size_t)m.x * C2 + lane]);
        float nm = __int_as_float(m.y);
        ax += v.x * nm;
        ay += v.y * nm;
    }

    float di = g_dinv[node];
    float d2 = di * di;
    float2 hv = h[(size_t)node * C2 + lane];
    float2 bv = ((const float2*)b)[lane];
    float2 o;
    o.x = ax + hv.x * d2 + bv.x;
    o.y = ay + hv.y * d2 + bv.y;
    out[(size_t)node * C2 + lane] = o;
}

// -------- CSR gather layer 2 + relu + classifier + log_softmax ---------------
// F=32: one warp per node, lane = feature column. Fully fused epilogue.
__global__ void k_gather32f(const float* __restrict__ b, const float* __restrict__ Wc,
                            const float* __restrict__ bc, float* __restrict__ outp,
                            int N) {
    constexpr int F = H2D;
    __shared__ float WcSm[H2D * NCLS];
    __shared__ float bcSm[NCLS];
    int tid = threadIdx.x;
    for (int i = tid; i < H2D * NCLS; i += blockDim.x) WcSm[i] = Wc[i];
    if (tid < NCLS) bcSm[tid] = bc[tid];
    __syncthreads();

    int node = blockIdx.x * (blockDim.x >> 5) + (tid >> 5);
    int lane = tid & 31;
    if (node >= N) return;  // warp-uniform

    const float* h = g_h2;
    int beg = g_off[node];
    int end = g_off[node + 1];

    float acc = 0.0f;
    int j = beg;
    for (; j + 3 < end; j += 4) {
        int2 m0 = __ldg(&g_edge[j + 0]);
        int2 m1 = __ldg(&g_edge[j + 1]);
        int2 m2 = __ldg(&g_edge[j + 2]);
        int2 m3 = __ldg(&g_edge[j + 3]);
        acc += __ldg(&h[(size_t)m0.x * F + lane]) * __int_as_float(m0.y);
        acc += __ldg(&h[(size_t)m1.x * F + lane]) * __int_as_float(m1.y);
        acc += __ldg(&h[(size_t)m2.x * F + lane]) * __int_as_float(m2.y);
        acc += __ldg(&h[(size_t)m3.x * F + lane]) * __int_as_float(m3.y);
    }
    for (; j < end; j++) {
        int2 m = __ldg(&g_edge[j]);
        acc += __ldg(&h[(size_t)m.x * F + lane]) * __int_as_float(m.y);
    }

    float di = g_dinv[node];
    float x = acc + h[(size_t)node * F + lane] * di * di + b[lane];
    x = fmaxf(x, 0.0f);  // relu before classifier

    // logits: lg[c] = sum_lane x * Wc[lane][c]  (warp butterfly on 10-vector)
    float p[NCLS];
#pragma unroll
    for (int c = 0; c < NCLS; c++) p[c] = x * WcSm[lane * NCLS + c];
#pragma unroll
    for (int s = 16; s > 0; s >>= 1)
#pragma unroll
        for (int c = 0; c < NCLS; c++)
            p[c] += __shfl_xor_sync(0xffffffffu, p[c], s);

    float lg[NCLS];
#pragma unroll
    for (int c = 0; c < NCLS; c++) lg[c] = p[c] + bcSm[c];
    float mx = lg[0];
#pragma unroll
    for (int c = 1; c < NCLS; c++) mx = fmaxf(mx, lg[c]);
    float sum = 0.0f;
#pragma unroll
    for (int c = 0; c < NCLS; c++) sum += __expf(lg[c] - mx);
    float lse = mx + logf(sum);

    if (lane < NCLS) outp[(size_t)node * NCLS + lane] = lg[lane] - lse;
}

// ---------------- launch (kernel launches ONLY) ------------------------------
extern "C" void kernel_launch(void* const* d_in, const int* in_sizes, int n_in,
                              void* d_out, int out_size) {
    const float* feat = (const float*)d_in[0];
    const int*   ei   = (const int*)d_in[1];    // int32 (JAX x64 disabled)
    const float* W1   = (const float*)d_in[2];
    const float* b1   = (const float*)d_in[3];
    const float* W2   = (const float*)d_in[4];
    const float* b2   = (const float*)d_in[5];
    const float* Wc   = (const float*)d_in[6];
    const float* bc   = (const float*)d_in[7];

    int N = in_sizes[0] / FIN;
    int E = in_sizes[1] / 2;

    const int T = 256;
    int nb = (N + SCAN_B - 1) / SCAN_B;
    int Eh = (E + 1) / 2;

    // CSR build
    k_zero<<<(N + T - 1) / T, T>>>(N);
    k_count<<<(Eh + T - 1) / T, T>>>(ei, E);
    k_scan1<<<nb, SCAN_B>>>(N);
    k_scan2<<<1, 256>>>(nb);
    k_scan3<<<(N + T - 1) / T, T>>>(N, E);
    k_fill<<<(Eh + T - 1) / T, T>>>(ei, E);

    // layer 1
    k_gemm<FIN, H1D, false, 1><<<(N + 15) / 16, 256>>>(feat, W1, N);
    k_gather64<<<(N + 7) / 8, 256>>>(b1, N);

    // layer 2 + fused classifier/log_softmax
    k_gemm<H1D, H2D, true, 2><<<(N + 31) / 32, 256>>>(nullptr, W2, N);
    k_gather32f<<<(N + 7) / 8, 256>>>(b2, Wc, bc, (float*)d_out, N);
}

// round 8
// speedup vs baseline: 1.0755x; 1.0736x over previous
#include <cuda_runtime.h>
#include <math.h>
#include <stdint.h>

#define MAX_E 3200000
#define MAX_N 100000
#define FIN 128
#define H1D 64
#define H2D 32
#define NCLS 10
#define SCAN_B 512
#define MAX_BLKS ((MAX_N + SCAN_B) / SCAN_B + 2)

// ---------------- scratch (device globals; referenced directly, no host APIs)
__device__ __align__(16) int   g_indeg[MAX_N];
__device__ __align__(16) int   g_off[MAX_N + 1];
__device__ __align__(16) int   g_pos[MAX_N];
__device__ __align__(16) int   g_part[MAX_N];
__device__ __align__(16) int   g_bsum[MAX_BLKS];
__device__ __align__(16) float g_dinv[MAX_N];
__device__ __align__(16) int   g_esrc[MAX_E];
__device__ __align__(16) float g_enorm[MAX_E];
__device__ __align__(16) float g_h1[MAX_N * H1D];
__device__ __align__(16) float g_a1[MAX_N * H1D];
__device__ __align__(16) float g_h2[MAX_N * H2D];
__device__ __align__(16) float g_a2[MAX_N * H2D];

// compile-time buffer selection per layer width
template <int F> struct Buf;
template <> struct Buf<H1D> {
    static __device__ __forceinline__ float* h() { return g_h1; }
    static __device__ __forceinline__ float* a() { return g_a1; }
};
template <> struct Buf<H2D> {
    static __device__ __forceinline__ float* h() { return g_h2; }
    static __device__ __forceinline__ float* a() { return g_a2; }
};

// ---------------- CSR build ---------------------------------------------------
__global__ void k_zero(int N) {
    int i = blockIdx.x * blockDim.x + threadIdx.x;
    if (i < N) g_indeg[i] = 0;
}

// edge_index is int32 (JAX default x64-disabled): row 0 = src, row 1 = dst
__global__ void k_count(const int* __restrict__ ei, int E) {
    int e = blockIdx.x * blockDim.x + threadIdx.x;
    if (e >= E) return;
    atomicAdd(&g_indeg[ei[e + E]], 1);
}

__global__ void k_scan1(int N) {
    __shared__ int sm[SCAN_B];
    int gid = blockIdx.x * SCAN_B + threadIdx.x;
    int v = (gid < N) ? g_indeg[gid] : 0;
    sm[threadIdx.x] = v;
    __syncthreads();
#pragma unroll
    for (int s = 1; s < SCAN_B; s <<= 1) {
        int t = (threadIdx.x >= (unsigned)s) ? sm[threadIdx.x - s] : 0;
        __syncthreads();
        sm[threadIdx.x] += t;
        __syncthreads();
    }
    if (gid < N) g_part[gid] = sm[threadIdx.x] - v;  // exclusive within block
    if (threadIdx.x == SCAN_B - 1) g_bsum[blockIdx.x] = sm[threadIdx.x];
}

// parallel exclusive scan of block sums (nb <= 256)  [only change vs R5]
__global__ void k_scan2(int nb) {
    __shared__ int sm[256];
    int t = threadIdx.x;
    int v = (t < nb) ? g_bsum[t] : 0;
    sm[t] = v;
    __syncthreads();
#pragma unroll
    for (int s = 1; s < 256; s <<= 1) {
        int u = (t >= (unsigned)s) ? sm[t - s] : 0;
        __syncthreads();
        sm[t] += u;
        __syncthreads();
    }
    if (t < nb) g_bsum[t] = sm[t] - v;  // exclusive
}

__global__ void k_scan3(int N, int E) {
    int gid = blockIdx.x * blockDim.x + threadIdx.x;
    if (gid < N) {
        int o = g_part[gid] + g_bsum[gid / SCAN_B];
        g_off[gid] = o;
        g_pos[gid] = o;
    }
    if (gid == 0) g_off[N] = E;
}

__global__ void k_dinv(int N) {
    int i = blockIdx.x * blockDim.x + threadIdx.x;
    if (i < N) g_dinv[i] = rsqrtf((float)g_indeg[i] + 1.0f);
}

__global__ void k_fill(const int* __restrict__ ei, int E) {
    int e = blockIdx.x * blockDim.x + threadIdx.x;
    if (e >= E) return;
    int s = ei[e];
    int d = ei[e + E];
    int p = atomicAdd(&g_pos[d], 1);
    g_esrc[p]  = s;
    g_enorm[p] = g_dinv[s] * g_dinv[d];
}

// ---------------- dense GEMM: out[N,ODIM] = (relu?)X[N,KDIM] @ W[KDIM,ODIM] --
// LAYER 1: X = feat param, out = g_h1. LAYER 2: X = g_a1, out = g_h2.
template <int KDIM, int ODIM, bool RELU_IN, int LAYER>
__global__ void k_gemm(const float* __restrict__ Xparam, const float* __restrict__ Wg,
                       int N) {
    const float* X  = (LAYER == 1) ? Xparam : g_a1;
    float*      out = (LAYER == 1) ? g_h1   : g_h2;

    constexpr int NL  = 256 / ODIM;   // row-lanes
    constexpr int RPT = 4;            // rows per thread
    constexpr int RPB = NL * RPT;     // rows per block
    __shared__ float Wsm[KDIM * ODIM];
    __shared__ float Xsm[RPB * KDIM];

    int tid = threadIdx.x;
    for (int i = tid; i < KDIM * ODIM; i += 256) Wsm[i] = Wg[i];

    int row0 = blockIdx.x * RPB;
    for (int i = tid; i < RPB * KDIM; i += 256) {
        int r = i / KDIM, k = i - r * KDIM;
        int gr = row0 + r;
        float v = (gr < N) ? X[(size_t)gr * KDIM + k] : 0.0f;
        if (RELU_IN) v = fmaxf(v, 0.0f);
        Xsm[i] = v;
    }
    __syncthreads();

    int col = tid % ODIM;
    int rl  = tid / ODIM;
    float acc[RPT];
#pragma unroll
    for (int j = 0; j < RPT; j++) acc[j] = 0.0f;

#pragma unroll 4
    for (int k = 0; k < KDIM; k++) {
        float w = Wsm[k * ODIM + col];
#pragma unroll
        for (int j = 0; j < RPT; j++)
            acc[j] += Xsm[(rl * RPT + j) * KDIM + k] * w;
    }
#pragma unroll
    for (int j = 0; j < RPT; j++) {
        int gr = row0 + rl * RPT + j;
        if (gr < N) out[(size_t)gr * ODIM + col] = acc[j];
    }
}

// -------- CSR gather: a[i] = sum_j h[src_j]*norm_j + h[i]*dinv[i]^2 + b ------
template <int F>
__global__ void k_gather(const float* __restrict__ b, int N) {
    const float* h  = Buf<F>::h();
    float*      out = Buf<F>::a();

    int node = blockIdx.x * (blockDim.x >> 5) + (threadIdx.x >> 5);
    int lane = threadIdx.x & 31;
    if (node >= N) return;

    int beg = g_off[node];
    int end = g_off[node + 1];

    constexpr int C = F / 32;
    float acc[C];
#pragma unroll
    for (int c = 0; c < C; c++) acc[c] = 0.0f;

    int j = beg;
    for (; j + 1 < end; j += 2) {          // 2-edge pipeline for MLP
        int   s0 = __ldg(&g_esrc[j]);
        int   s1 = __ldg(&g_esrc[j + 1]);
        float n0 = __ldg(&g_enorm[j]);
        float n1 = __ldg(&g_enorm[j + 1]);
        const float* r0 = h + (size_t)s0 * F;
        const float* r1 = h + (size_t)s1 * F;
#pragma unroll
        for (int c = 0; c < C; c++) {
            acc[c] += __ldg(&r0[lane + 32 * c]) * n0;
            acc[c] += __ldg(&r1[lane + 32 * c]) * n1;
        }
    }
    if (j < end) {
        int   s0 = __ldg(&g_esrc[j]);
        float n0 = __ldg(&g_enorm[j]);
        const float* r0 = h + (size_t)s0 * F;
#pragma unroll
        for (int c = 0; c < C; c++) acc[c] += __ldg(&r0[lane + 32 * c]) * n0;
    }

    float di = g_dinv[node];
    float d2 = di * di;
    const float* hr = h + (size_t)node * F;
#pragma unroll
    for (int c = 0; c < C; c++) {
        int col = lane + 32 * c;
        out[(size_t)node * F + col] = acc[c] + hr[col] * d2 + b[col];
    }
}

// ---------------- classifier + log_softmax -----------------------------------
__global__ void k_final(const float* __restrict__ Wc, const float* __restrict__ bc,
                        float* __restrict__ out, int N) {
    __shared__ float Wsm[H2D * NCLS];
    __shared__ float bsm[NCLS];
    int tid = threadIdx.x;
    for (int i = tid; i < H2D * NCLS; i += blockDim.x) Wsm[i] = Wc[i];
    if (tid < NCLS) bsm[tid] = bc[tid];
    __syncthreads();

    int i = blockIdx.x * blockDim.x + tid;
    if (i >= N) return;

    float x[H2D];
    const float4* row = (const float4*)(g_a2 + (size_t)i * H2D);
#pragma unroll
    for (int k = 0; k < H2D / 4; k++) {
        float4 v = row[k];
        x[4 * k + 0] = fmaxf(v.x, 0.0f);
        x[4 * k + 1] = fmaxf(v.y, 0.0f);
        x[4 * k + 2] = fmaxf(v.z, 0.0f);
        x[4 * k + 3] = fmaxf(v.w, 0.0f);
    }

    float lg[NCLS];
#pragma unroll
    for (int c = 0; c < NCLS; c++) {
        float acc = bsm[c];
#pragma unroll
        for (int k = 0; k < H2D; k++) acc += x[k] * Wsm[k * NCLS + c];
        lg[c] = acc;
    }
    float mx = lg[0];
#pragma unroll
    for (int c = 1; c < NCLS; c++) mx = fmaxf(mx, lg[c]);
    float sum = 0.0f;
#pragma unroll
    for (int c = 0; c < NCLS; c++) sum += __expf(lg[c] - mx);
    float lse = mx + logf(sum);
#pragma unroll
    for (int c = 0; c < NCLS; c++) out[(size_t)i * NCLS + c] = lg[c] - lse;
}

// ---------------- launch (kernel launches ONLY; graph-capture clean) ---------
extern "C" void kernel_launch(void* const* d_in, const int* in_sizes, int n_in,
                              void* d_out, int out_size) {
    const float* feat = (const float*)d_in[0];
    const int*   ei   = (const int*)d_in[1];    // int32! (JAX x64 disabled)
    const float* W1   = (const float*)d_in[2];
    const float* b1   = (const float*)d_in[3];
    const float* W2   = (const float*)d_in[4];
    const float* b2   = (const float*)d_in[5];
    const float* Wc   = (const float*)d_in[6];
    const float* bc   = (const float*)d_in[7];

    int N = in_sizes[0] / FIN;
    int E = in_sizes[1] / 2;

    const int T = 256;
    int nb = (N + SCAN_B - 1) / SCAN_B;

    // CSR build
    k_zero<<<(N + T - 1) / T, T>>>(N);
    k_count<<<(E + T - 1) / T, T>>>(ei, E);
    k_scan1<<<nb, SCAN_B>>>(N);
    k_scan2<<<1, 256>>>(nb);
    k_scan3<<<(N + T - 1) / T, T>>>(N, E);
    k_dinv<<<(N + T - 1) / T, T>>>(N);
    k_fill<<<(E + T - 1) / T, T>>>(ei, E);

    // layer 1
    k_gemm<FIN, H1D, false, 1><<<(N + 15) / 16, 256>>>(feat, W1, N);
    k_gather<H1D><<<(N + 7) / 8, 256>>>(b1, N);

    // layer 2
    k_gemm<H1D, H2D, true, 2><<<(N + 31) / 32, 256>>>(nullptr, W2, N);
    k_gather<H2D><<<(N + 7) / 8, 256>>>(b2, N);

    // classifier + log_softmax
    k_final<<<(N + 127) / 128, 128>>>(Wc, bc, (float*)d_out, N);
}

// round 9
// speedup vs baseline: 1.0886x; 1.0122x over previous
#include <cuda_runtime.h>
#include <math.h>
#include <stdint.h>

#define MAX_E 3200000
#define MAX_N 100000
#define FIN 128
#define H1D 64
#define H2D 32
#define NCLS 10
#define SCAN_B 512
#define MAX_BLKS ((MAX_N + SCAN_B) / SCAN_B + 2)

// ---------------- scratch (device globals; referenced directly, no host APIs)
__device__ __align__(16) int   g_indeg[MAX_N];
__device__ __align__(16) int   g_off[MAX_N + 1];
__device__ __align__(16) int   g_pos[MAX_N];
__device__ __align__(16) int   g_part[MAX_N];
__device__ __align__(16) int   g_bsum[MAX_BLKS];
__device__ __align__(16) float g_dinv[MAX_N];
__device__ __align__(16) int   g_esrc[MAX_E];
__device__ __align__(16) float g_enorm[MAX_E];
__device__ __align__(16) float g_h1[MAX_N * H1D];
__device__ __align__(16) float g_a1[MAX_N * H1D];
__device__ __align__(16) float g_h2[MAX_N * H2D];
__device__ __align__(16) float g_a2[MAX_N * H2D];

// ---------------- CSR build ---------------------------------------------------
__global__ void k_zero(int N) {
    int i = blockIdx.x * blockDim.x + threadIdx.x;
    if (i < N) g_indeg[i] = 0;
}

// edge_index is int32 (JAX default x64-disabled): row 0 = src, row 1 = dst
__global__ void k_count(const int* __restrict__ ei, int E) {
    int e = blockIdx.x * blockDim.x + threadIdx.x;
    if (e >= E) return;
    atomicAdd(&g_indeg[ei[e + E]], 1);
}

__global__ void k_scan1(int N) {
    __shared__ int sm[SCAN_B];
    int gid = blockIdx.x * SCAN_B + threadIdx.x;
    int v = (gid < N) ? g_indeg[gid] : 0;
    sm[threadIdx.x] = v;
    __syncthreads();
#pragma unroll
    for (int s = 1; s < SCAN_B; s <<= 1) {
        int t = (threadIdx.x >= (unsigned)s) ? sm[threadIdx.x - s] : 0;
        __syncthreads();
        sm[threadIdx.x] += t;
        __syncthreads();
    }
    if (gid < N) g_part[gid] = sm[threadIdx.x] - v;  // exclusive within block
    if (threadIdx.x == SCAN_B - 1) g_bsum[blockIdx.x] = sm[threadIdx.x];
}

// parallel exclusive scan of block sums (nb <= 256)
__global__ void k_scan2(int nb) {
    __shared__ int sm[256];
    int t = threadIdx.x;
    int v = (t < nb) ? g_bsum[t] : 0;
    sm[t] = v;
    __syncthreads();
#pragma unroll
    for (int s = 1; s < 256; s <<= 1) {
        int u = (t >= (unsigned)s) ? sm[t - s] : 0;
        __syncthreads();
        sm[t] += u;
        __syncthreads();
    }
    if (t < nb) g_bsum[t] = sm[t] - v;  // exclusive
}

__global__ void k_scan3(int N, int E) {
    int gid = blockIdx.x * blockDim.x + threadIdx.x;
    if (gid < N) {
        int o = g_part[gid] + g_bsum[gid / SCAN_B];
        g_off[gid] = o;
        g_pos[gid] = o;
    }
    if (gid == 0) g_off[N] = E;
}

__global__ void k_dinv(int N) {
    int i = blockIdx.x * blockDim.x + threadIdx.x;
    if (i < N) g_dinv[i] = rsqrtf((float)g_indeg[i] + 1.0f);
}

__global__ void k_fill(const int* __restrict__ ei, int E) {
    int e = blockIdx.x * blockDim.x + threadIdx.x;
    if (e >= E) return;
    int s = ei[e];
    int d = ei[e + E];
    int p = atomicAdd(&g_pos[d], 1);
    g_esrc[p]  = s;
    g_enorm[p] = g_dinv[s] * g_dinv[d];
}

// ---------------- dense GEMM: out[N,ODIM] = (relu?)X[N,KDIM] @ W[KDIM,ODIM] --
// LAYER 1: X = feat param, out = g_h1. LAYER 2: X = g_a1, out = g_h2.
template <int KDIM, int ODIM, bool RELU_IN, int LAYER>
__global__ void k_gemm(const float* __restrict__ Xparam, const float* __restrict__ Wg,
                       int N) {
    const float* X  = (LAYER == 1) ? Xparam : g_a1;
    float*      out = (LAYER == 1) ? g_h1   : g_h2;

    constexpr int NL  = 256 / ODIM;   // row-lanes
    constexpr int RPT = 4;            // rows per thread
    constexpr int RPB = NL * RPT;     // rows per block
    __shared__ float Wsm[KDIM * ODIM];
    __shared__ float Xsm[RPB * KDIM];

    int tid = threadIdx.x;
    for (int i = tid; i < KDIM * ODIM; i += 256) Wsm[i] = Wg[i];

    int row0 = blockIdx.x * RPB;
    for (int i = tid; i < RPB * KDIM; i += 256) {
        int r = i / KDIM, k = i - r * KDIM;
        int gr = row0 + r;
        float v = (gr < N) ? X[(size_t)gr * KDIM + k] : 0.0f;
        if (RELU_IN) v = fmaxf(v, 0.0f);
        Xsm[i] = v;
    }
    __syncthreads();

    int col = tid % ODIM;
    int rl  = tid / ODIM;
    float acc[RPT];
#pragma unroll
    for (int j = 0; j < RPT; j++) acc[j] = 0.0f;

#pragma unroll 4
    for (int k = 0; k < KDIM; k++) {
        float w = Wsm[k * ODIM + col];
#pragma unroll
        for (int j = 0; j < RPT; j++)
            acc[j] += Xsm[(rl * RPT + j) * KDIM + k] * w;
    }
#pragma unroll
    for (int j = 0; j < RPT; j++) {
        int gr = row0 + rl * RPT + j;
        if (gr < N) out[(size_t)gr * ODIM + col] = acc[j];
    }
}

// -------- CSR gather layer 1 (F=64): float2 per lane -------------------------
// a1[i] = sum_j h1[src_j]*norm_j + h1[i]*dinv[i]^2 + b1
__global__ void k_gather64(const float* __restrict__ b, int N) {
    const float2* h = (const float2*)g_h1;
    float2*     out = (float2*)g_a1;
    constexpr int C2 = H1D / 2;   // 32 float2 per row: one per lane

    int node = blockIdx.x * (blockDim.x >> 5) + (threadIdx.x >> 5);
    int lane = threadIdx.x & 31;
    if (node >= N) return;

    int beg = g_off[node];
    int end = g_off[node + 1];

    float ax = 0.0f, ay = 0.0f;
    int j = beg;
    for (; j + 1 < end; j += 2) {          // 2-edge pipeline for MLP
        int   s0 = __ldg(&g_esrc[j]);
        int   s1 = __ldg(&g_esrc[j + 1]);
        float n0 = __ldg(&g_enorm[j]);
        float n1 = __ldg(&g_enorm[j + 1]);
        float2 v0 = __ldg(&h[(size_t)s0 * C2 + lane]);
        float2 v1 = __ldg(&h[(size_t)s1 * C2 + lane]);
        ax += v0.x * n0 + v1.x * n1;
        ay += v0.y * n0 + v1.y * n1;
    }
    if (j < end) {
        int   s0 = __ldg(&g_esrc[j]);
        float n0 = __ldg(&g_enorm[j]);
        float2 v0 = __ldg(&h[(size_t)s0 * C2 + lane]);
        ax += v0.x * n0;
        ay += v0.y * n0;
    }

    float di = g_dinv[node];
    float d2 = di * di;
    float2 hv = h[(size_t)node * C2 + lane];
    float2 bv = ((const float2*)b)[lane];
    float2 o;
    o.x = ax + hv.x * d2 + bv.x;
    o.y = ay + hv.y * d2 + bv.y;
    out[(size_t)node * C2 + lane] = o;
}

// -------- CSR gather layer 2 (F=32): scalar per lane (R8-proven) -------------
__global__ void k_gather32(const float* __restrict__ b, int N) {
    const float* h  = g_h2;
    float*      out = g_a2;
    constexpr int F = H2D;

    int node = blockIdx.x * (blockDim.x >> 5) + (threadIdx.x >> 5);
    int lane = threadIdx.x & 31;
    if (node >= N) return;

    int beg = g_off[node];
    int end = g_off[node + 1];

    float acc = 0.0f;
    int j = beg;
    for (; j + 1 < end; j += 2) {
        int   s0 = __ldg(&g_esrc[j]);
        int   s1 = __ldg(&g_esrc[j + 1]);
        float n0 = __ldg(&g_enorm[j]);
        float n1 = __ldg(&g_enorm[j + 1]);
        acc += __ldg(&h[(size_t)s0 * F + lane]) * n0;
        acc += __ldg(&h[(size_t)s1 * F + lane]) * n1;
    }
    if (j < end) {
        int   s0 = __ldg(&g_esrc[j]);
        float n0 = __ldg(&g_enorm[j]);
        acc += __ldg(&h[(size_t)s0 * F + lane]) * n0;
    }

    float di = g_dinv[node];
    float d2 = di * di;
    out[(size_t)node * F + lane] = acc + h[(size_t)node * F + lane] * d2 + b[lane];
}

// ---------------- classifier + log_softmax -----------------------------------
__global__ void k_final(const float* __restrict__ Wc, const float* __restrict__ bc,
                        float* __restrict__ out, int N) {
    __shared__ float Wsm[H2D * NCLS];
    __shared__ float bsm[NCLS];
    int tid = threadIdx.x;
    for (int i = tid; i < H2D * NCLS; i += blockDim.x) Wsm[i] = Wc[i];
    if (tid < NCLS) bsm[tid] = bc[tid];
    __syncthreads();

    int i = blockIdx.x * blockDim.x + tid;
    if (i >= N) return;

    float x[H2D];
    const float4* row = (const float4*)(g_a2 + (size_t)i * H2D);
#pragma unroll
    for (int k = 0; k < H2D / 4; k++) {
        float4 v = row[k];
        x[4 * k + 0] = fmaxf(v.x, 0.0f);
        x[4 * k + 1] = fmaxf(v.y, 0.0f);
        x[4 * k + 2] = fmaxf(v.z, 0.0f);
        x[4 * k + 3] = fmaxf(v.w, 0.0f);
    }

    float lg[NCLS];
#pragma unroll
    for (int c = 0; c < NCLS; c++) {
        float acc = bsm[c];
#pragma unroll
        for (int k = 0; k < H2D; k++) acc += x[k] * Wsm[k * NCLS + c];
        lg[c] = acc;
    }
    float mx = lg[0];
#pragma unroll
    for (int c = 1; c < NCLS; c++) mx = fmaxf(mx, lg[c]);
    float sum = 0.0f;
#pragma unroll
    for (int c = 0; c < NCLS; c++) sum += __expf(lg[c] - mx);
    float lse = mx + logf(sum);
#pragma unroll
    for (int c = 0; c < NCLS; c++) out[(size_t)i * NCLS + c] = lg[c] - lse;
}

// ---------------- launch (kernel launches ONLY; graph-capture clean) ---------
extern "C" void kernel_launch(void* const* d_in, const int* in_sizes, int n_in,
                              void* d_out, int out_size) {
    const float* feat = (const float*)d_in[0];
    const int*   ei   = (const int*)d_in[1];    // int32! (JAX x64 disabled)
    const float* W1   = (const float*)d_in[2];
    const float* b1   = (const float*)d_in[3];
    const float* W2   = (const float*)d_in[4];
    const float* b2   = (const float*)d_in[5];
    const float* Wc   = (const float*)d_in[6];
    const float* bc   = (const float*)d_in[7];

    int N = in_sizes[0] / FIN;
    int E = in_sizes[1] / 2;

    const int T = 256;
    int nb = (N + SCAN_B - 1) / SCAN_B;

    // CSR build
    k_zero<<<(N + T - 1) / T, T>>>(N);
    k_count<<<(E + T - 1) / T, T>>>(ei, E);
    k_scan1<<<nb, SCAN_B>>>(N);
    k_scan2<<<1, 256>>>(nb);
    k_scan3<<<(N + T - 1) / T, T>>>(N, E);
    k_dinv<<<(N + T - 1) / T, T>>>(N);
    k_fill<<<(E + T - 1) / T, T>>>(ei, E);

    // layer 1
    k_gemm<FIN, H1D, false, 1><<<(N + 15) / 16, 256>>>(feat, W1, N);
    k_gather64<<<(N + 7) / 8, 256>>>(b1, N);

    // layer 2
    k_gemm<H1D, H2D, true, 2><<<(N + 31) / 32, 256>>>(nullptr, W2, N);
    k_gather32<<<(N + 7) / 8, 256>>>(b2, N);

    // classifier + log_softmax
    k_final<<<(N + 127) / 128, 128>>>(Wc, bc, (float*)d_out, N);
}